// round 16
// baseline (speedup 1.0000x reference)
#include <cuda_runtime.h>
#include <cuda_bf16.h>
#include <math.h>
#include <stdint.h>

#define LN_EPS 1e-5f

// Problem constants
constexpr int CB = 4, CS = 2048, CD = 2048, CF = 8192;
constexpr int CM = CB * CS;
constexpr int MCHUNK = 2048;
constexpr int NCHUNKS = CM / MCHUNK;

// GEMM tiling: 128x64 tile, 512 threads = 16 warps as 8(M) x 2(N).
constexpr int BM = 128, BN = 64, BK = 32;
constexpr int THREADS = 512;
constexpr int RW = 16;           // smem row pitch in words (swizzled, no pad)

// Smem (words): per stage, 6 A planes (rh,rl,ih,il,sh,sl) then 6 B planes.
constexpr int A_PL = BM * RW;                // 2048 words
constexpr int B_PL = BN * RW;                // 1024 words
constexpr int B_OFF = 6 * A_PL;              // 12288
constexpr int STAGE_W = 6 * A_PL + 6 * B_PL; // 18432 words
constexpr int SMEM_BYTES = 2 * STAGE_W * 4;  // 147456 B -> 1 CTA/SM, 16 warps

// ---- device-global scratch: packed bf16x2 planes (word = k,k+1) ----
constexpr size_t XW = (size_t)CM * CD / 2;
constexpr size_t WW = (size_t)CF * CD / 2;
constexpr size_t UW = (size_t)MCHUNK * CF / 2;
__device__ __align__(16) uint32_t g_cX_hr[XW], g_cX_lr[XW], g_cX_hi[XW], g_cX_li[XW], g_cX_hs[XW], g_cX_ls[XW];
__device__ __align__(16) uint32_t g_cWu_hr[WW], g_cWu_lr[WW], g_cWu_hi[WW], g_cWu_li[WW], g_cWu_hs[WW], g_cWu_ls[WW];
__device__ __align__(16) uint32_t g_cWd_hr[WW], g_cWd_lr[WW], g_cWd_hi[WW], g_cWd_li[WW], g_cWd_hs[WW], g_cWd_ls[WW];
__device__ __align__(16) uint32_t g_cUp_hr[UW], g_cUp_lr[UW], g_cUp_hi[UW], g_cUp_li[UW], g_cUp_hs[UW], g_cUp_ls[UW];
__device__ __align__(16) float g_dn_re[(size_t)MCHUNK * CD];
__device__ __align__(16) float g_dn_im[(size_t)MCHUNK * CD];

// Split two fp32 into packed bf16 hi / lo words
__device__ __forceinline__ void split2(float x, float y, uint32_t& hi, uint32_t& lo) {
    __nv_bfloat16 xh = __float2bfloat16_rn(x);
    __nv_bfloat16 yh = __float2bfloat16_rn(y);
    float xr = x - __bfloat162float(xh);
    float yr = y - __bfloat162float(yh);
    __nv_bfloat16 xl = __float2bfloat16_rn(xr);
    __nv_bfloat16 yl = __float2bfloat16_rn(yr);
    hi = (uint32_t)__bfloat16_as_ushort(xh) | ((uint32_t)__bfloat16_as_ushort(yh) << 16);
    lo = (uint32_t)__bfloat16_as_ushort(xl) | ((uint32_t)__bfloat16_as_ushort(yl) << 16);
}

__device__ __forceinline__ void mma16816(float* c, const uint32_t* a, const uint32_t* b) {
    asm volatile(
        "mma.sync.aligned.m16n8k16.row.col.f32.bf16.bf16.f32 "
        "{%0,%1,%2,%3}, {%4,%5,%6,%7}, {%8,%9}, {%0,%1,%2,%3};\n"
        : "+f"(c[0]), "+f"(c[1]), "+f"(c[2]), "+f"(c[3])
        : "r"(a[0]), "r"(a[1]), "r"(a[2]), "r"(a[3]), "r"(b[0]), "r"(b[1]));
}

#define LDSM4(r, addr) \
    asm volatile("ldmatrix.sync.aligned.m8n8.x4.shared.b16 {%0,%1,%2,%3}, [%4];" \
        : "=r"((r)[0]), "=r"((r)[1]), "=r"((r)[2]), "=r"((r)[3]) : "r"(addr))

__device__ __forceinline__ void cpasync16(uint32_t smem_bytes_addr, const void* g) {
    asm volatile("cp.async.cg.shared.global [%0], [%1], 16;\n"
                 :: "r"(smem_bytes_addr), "l"(g));
}
#define CP_COMMIT() asm volatile("cp.async.commit_group;\n")
template <int N>
__device__ __forceinline__ void cp_wait() {
    asm volatile("cp.async.wait_group %0;\n" :: "n"(N));
}

// Pre-conversion: fp32 planar -> packed bf16x2 planes (re, im, sum).
__global__ void __launch_bounds__(256)
conv_kernel(const float* __restrict__ re, const float* __restrict__ im,
            uint32_t* __restrict__ hr, uint32_t* __restrict__ lr,
            uint32_t* __restrict__ hi_, uint32_t* __restrict__ li,
            uint32_t* __restrict__ hs, uint32_t* __restrict__ ls,
            size_t nwords, size_t lim) {
    size_t i = (size_t)blockIdx.x * 256 + threadIdx.x;
    if (i >= nwords) return;
    size_t e = 2 * i;
    float r0 = 0.f, r1 = 0.f, q0 = 0.f, q1 = 0.f;
    if (e + 2 <= lim) {
        float2 v = *reinterpret_cast<const float2*>(re + e);
        float2 w = *reinterpret_cast<const float2*>(im + e);
        r0 = v.x; r1 = v.y; q0 = w.x; q1 = w.y;
    }
    split2(r0, r1, hr[i], lr[i]);
    split2(q0, q1, hi_[i], li[i]);
    split2(r0 + q0, r1 + q1, hs[i], ls[i]);
}

// Complex NT GEMM, Karatsuba: P1=ar*br, P2=ai*bi, P3=(ar+ai)(br+bi);
// re=P1-P2, im=P3-P1-P2.  9 MMAs per k16 per (16x8) output tile.
// PHASE 0: A = g_cX (rows m_base+..), B = g_cWu, epi bias+modrelu -> g_cUp (6 planes)
// PHASE 1: A = g_cUp (chunk-local), B = g_cWd, epi plain -> g_dn
template <int PHASE>
__global__ void __launch_bounds__(THREADS, 1)
cgemm_nt(const float* __restrict__ bias_re, const float* __restrict__ bias_im,
         const float* __restrict__ mrb,
         int m_base, int N, int K, size_t bias_lim) {
    extern __shared__ uint32_t s[];
    const uint32_t smem_b = (uint32_t)__cvta_generic_to_shared(s);

    const int tid = threadIdx.x;
    const int lane = tid & 31;
    const int warp = tid >> 5;     // 0..15
    const int wm = warp >> 1;      // 0..7  (M: 16-row slab)
    const int wn = warp & 1;       // 0..1  (N: 32-col slab)
    const int g  = lane >> 2;
    const int tg = lane & 3;
    const int m0 = blockIdx.y * BM;
    const int n0 = blockIdx.x * BN;

    const uint32_t* Apl[6];
    const uint32_t* Bpl[6];
    int a_row0;
    if (PHASE == 0) {
        Apl[0] = g_cX_hr; Apl[1] = g_cX_lr; Apl[2] = g_cX_hi;
        Apl[3] = g_cX_li; Apl[4] = g_cX_hs; Apl[5] = g_cX_ls;
        Bpl[0] = g_cWu_hr; Bpl[1] = g_cWu_lr; Bpl[2] = g_cWu_hi;
        Bpl[3] = g_cWu_li; Bpl[4] = g_cWu_hs; Bpl[5] = g_cWu_ls;
        a_row0 = m_base;
    } else {
        Apl[0] = g_cUp_hr; Apl[1] = g_cUp_lr; Apl[2] = g_cUp_hi;
        Apl[3] = g_cUp_li; Apl[4] = g_cUp_hs; Apl[5] = g_cUp_ls;
        Bpl[0] = g_cWd_hr; Bpl[1] = g_cWd_lr; Bpl[2] = g_cWd_hi;
        Bpl[3] = g_cWd_li; Bpl[4] = g_cWd_hs; Bpl[5] = g_cWd_ls;
        a_row0 = 0;
    }
    const int rw = K / 2;  // global plane row length in words

    const int lrow = lane & 7;
    const int quad = lane >> 3;

    // A-side ldmatrix offsets: quad = (chunk<<1)|rowhalf -> regs in mma order.
    int offA[2];
    {
        const int rselA = ((quad & 1) << 3) + lrow;
        const int cselA = quad >> 1;
        int r = wm * 16 + rselA;
#pragma unroll
        for (int ks = 0; ks < 2; ks++)
            offA[ks] = r * RW + (((ks * 2 + cselA) ^ ((r >> 1) & 3)) << 2);
    }
    // B-side ldmatrix offsets: quad = (rowblock<<1)|chunk -> permute-free.
    int offB[2][2];
    {
        const int rselB = ((quad >> 1) << 3) + lrow;
        const int cselB = quad & 1;
#pragma unroll
        for (int p = 0; p < 2; p++) {
            int r = wn * 32 + p * 16 + rselB;
#pragma unroll
            for (int ks = 0; ks < 2; ks++)
                offB[p][ks] = r * RW + (((ks * 2 + cselB) ^ ((r >> 1) & 3)) << 2);
        }
    }

    float accP1[4][4], accP2[4][4], accP3[4][4];
#pragma unroll
    for (int ni = 0; ni < 4; ni++)
#pragma unroll
        for (int r = 0; r < 4; r++) { accP1[ni][r] = 0.f; accP2[ni][r] = 0.f; accP3[ni][r] = 0.f; }

    // Stage loader: A 6*128*4 + B 6*64*4 = 4608 16B chunks / 512 threads = 9.
    auto load_stage = [&](int buf, int k0) {
        const int kw0 = k0 >> 1;
        const uint32_t sb = smem_b + (uint32_t)buf * STAGE_W * 4;
#pragma unroll
        for (int t = 0; t < 9; t++) {
            int c = tid + t * THREADS;       // 0..4607
            const uint32_t* src;
            uint32_t dst;
            if (c < 3072) {                  // A: plane = c>>9, row = (c>>2)&127
                int p = c >> 9;
                int r = (c >> 2) & 127;
                int kc = c & 3;
                src = Apl[p] + (size_t)(a_row0 + m0 + r) * rw + kw0 + kc * 4;
                int w = r * RW + ((kc ^ ((r >> 1) & 3)) << 2);
                dst = sb + (uint32_t)(p * A_PL + w) * 4;
            } else {                         // B
                int c2 = c - 3072;
                int p = c2 >> 8;
                int r = (c2 >> 2) & 63;
                int kc = c2 & 3;
                src = Bpl[p] + (size_t)(n0 + r) * rw + kw0 + kc * 4;
                int w = r * RW + ((kc ^ ((r >> 1) & 3)) << 2);
                dst = sb + (uint32_t)(B_OFF + p * B_PL + w) * 4;
            }
            cpasync16(dst, src);
        }
        CP_COMMIT();
    };

    const int NK = K / BK;
    load_stage(0, 0);

    for (int it = 0; it < NK; it++) {
        if (it + 1 < NK) {
            load_stage((it + 1) & 1, (it + 1) * BK);
            cp_wait<1>();
        } else {
            cp_wait<0>();
        }
        __syncthreads();

        const uint32_t sb = smem_b + (uint32_t)((it & 1) * STAGE_W) * 4;

#pragma unroll
        for (int ks = 0; ks < 2; ks++) {
            // A fragments: 6 planes, one 16-row slab each.
            uint32_t Arh[4], Arl[4], Aih[4], Ail[4], Ash[4], Asl[4];
            {
                const uint32_t a = sb + (uint32_t)offA[ks] * 4;
                LDSM4(Arh, a);
                LDSM4(Arl, a + A_PL * 4);
                LDSM4(Aih, a + 2 * A_PL * 4);
                LDSM4(Ail, a + 3 * A_PL * 4);
                LDSM4(Ash, a + 4 * A_PL * 4);
                LDSM4(Asl, a + 5 * A_PL * 4);
            }
            // B fragments per 16-row pair p (regs [0..1]=frag ni=2p, [2..3]=ni=2p+1)
#pragma unroll
            for (int p = 0; p < 2; p++) {
                uint32_t Brh[4], Brl[4], Bih[4], Bil[4], Bsh[4], Bsl[4];
                const uint32_t b = sb + (uint32_t)(B_OFF + offB[p][ks]) * 4;
                LDSM4(Brh, b);
                LDSM4(Brl, b + B_PL * 4);
                LDSM4(Bih, b + 2 * B_PL * 4);
                LDSM4(Bil, b + 3 * B_PL * 4);
                LDSM4(Bsh, b + 4 * B_PL * 4);
                LDSM4(Bsl, b + 5 * B_PL * 4);
#pragma unroll
                for (int q = 0; q < 2; q++) {
                    const int ni = 2 * p + q;
                    mma16816(accP1[ni], Arh, &Brh[2 * q]);
                    mma16816(accP1[ni], Arh, &Brl[2 * q]);
                    mma16816(accP1[ni], Arl, &Brh[2 * q]);
                    mma16816(accP2[ni], Aih, &Bih[2 * q]);
                    mma16816(accP2[ni], Aih, &Bil[2 * q]);
                    mma16816(accP2[ni], Ail, &Bih[2 * q]);
                    mma16816(accP3[ni], Ash, &Bsh[2 * q]);
                    mma16816(accP3[ni], Ash, &Bsl[2 * q]);
                    mma16816(accP3[ni], Asl, &Bsh[2 * q]);
                }
            }
        }
        __syncthreads();
    }

    // ---- epilogue: re = P1-P2, im = P3-P1-P2 ----
    const bool bias_ok = (PHASE != 0) || ((size_t)n0 + BN <= bias_lim);
#pragma unroll
    for (int ni = 0; ni < 4; ni++) {
        const int col = n0 + wn * 32 + ni * 8 + 2 * tg;   // even
#pragma unroll
        for (int h = 0; h < 2; h++) {
            const int row = m0 + wm * 16 + g + h * 8;
            float p10 = accP1[ni][2 * h], p11 = accP1[ni][2 * h + 1];
            float p20 = accP2[ni][2 * h], p21 = accP2[ni][2 * h + 1];
            float p30 = accP3[ni][2 * h], p31 = accP3[ni][2 * h + 1];
            float re0 = p10 - p20, re1 = p11 - p21;
            float im0 = p30 - p10 - p20, im1 = p31 - p11 - p21;
            if (PHASE == 0) {
                float br0 = 0.f, br1 = 0.f, bi0 = 0.f, bi1 = 0.f, mb0 = 0.f, mb1 = 0.f;
                if (bias_ok) {
                    br0 = bias_re[col]; br1 = bias_re[col + 1];
                    bi0 = bias_im[col]; bi1 = bias_im[col + 1];
                    mb0 = mrb[col];     mb1 = mrb[col + 1];
                }
                re0 += br0; im0 += bi0; re1 += br1; im1 += bi1;
                float mag0 = sqrtf(re0 * re0 + im0 * im0);
                float mag1 = sqrtf(re1 * re1 + im1 * im1);
                float s0 = fmaxf(mag0 + mb0, 0.f) / (mag0 + LN_EPS);
                float s1 = fmaxf(mag1 + mb1, 0.f) / (mag1 + LN_EPS);
                re0 *= s0; im0 *= s0; re1 *= s1; im1 *= s1;
                const size_t wo = (size_t)row * (N / 2) + (col >> 1);
                split2(re0, re1, g_cUp_hr[wo], g_cUp_lr[wo]);
                split2(im0, im1, g_cUp_hi[wo], g_cUp_li[wo]);
                split2(re0 + im0, re1 + im1, g_cUp_hs[wo], g_cUp_ls[wo]);
            } else {
                const size_t off = (size_t)row * N + col;
                *reinterpret_cast<float2*>(g_dn_re + off) = make_float2(re0, re1);
                *reinterpret_cast<float2*>(g_dn_im + off) = make_float2(im0, im1);
            }
        }
    }
}

// Complex LayerNorm over D + residual, one block per (chunk-local) token row.
template <int OUT_MODE>
__global__ void __launch_bounds__(256)
ln_res_kernel(const float* __restrict__ xr, const float* __restrict__ xi,
              const float* __restrict__ gr, const float* __restrict__ gi,
              const float* __restrict__ br, const float* __restrict__ bi,
              float* __restrict__ out, int m_base,
              size_t x_lim, size_t p_lim, size_t out_cap) {
    const int m = blockIdx.x;
    const size_t base = (size_t)m * CD;
    const size_t gbase = (size_t)(m_base + m) * CD;
    const int tid = threadIdx.x;
    const bool x_ok = (gbase + CD) <= x_lim;
    const bool p_ok = (size_t)CD <= p_lim;

    float sr = 0.f, si = 0.f, sq = 0.f;
    for (int d = tid; d < CD; d += 256) {
        float r = g_dn_re[base + d];
        float q = g_dn_im[base + d];
        sr += r; si += q; sq += r * r + q * q;
    }
    __shared__ float red0[256], red1[256], red2[256];
    red0[tid] = sr; red1[tid] = si; red2[tid] = sq;
    __syncthreads();
    for (int st = 128; st > 0; st >>= 1) {
        if (tid < st) {
            red0[tid] += red0[tid + st];
            red1[tid] += red1[tid + st];
            red2[tid] += red2[tid + st];
        }
        __syncthreads();
    }
    const float inv_d = 1.f / (float)CD;
    const float mur = red0[0] * inv_d;
    const float mui = red1[0] * inv_d;
    const float var = red2[0] * inv_d - (mur * mur + mui * mui);
    const float rstd = rsqrtf(var + LN_EPS);

    for (int d = tid; d < CD; d += 256) {
        float zr = (g_dn_re[base + d] - mur) * rstd;
        float zi = (g_dn_im[base + d] - mui) * rstd;
        float g_r = p_ok ? gr[d] : 1.f;
        float g_i = p_ok ? gi[d] : 0.f;
        float b_r = p_ok ? br[d] : 0.f;
        float b_i = p_ok ? bi[d] : 0.f;
        float xre = x_ok ? xr[gbase + d] : 0.f;
        float xim = x_ok ? xi[gbase + d] : 0.f;
        float o_r = g_r * zr - g_i * zi + b_r + xre;
        float o_i = g_r * zi + g_i * zr + b_i + xim;
        if (OUT_MODE == 0) {
            const size_t fo = gbase + d;
            if (fo < out_cap) out[fo] = o_r;
        } else {
            const size_t fo = 2 * (gbase + d);
            if (fo + 1 < out_cap) { out[fo] = o_r; out[fo + 1] = o_i; }
        }
    }
}

// ---------------- host-side binding ----------------
static bool match_sig(const int* s, const long long* want, long long scale) {
    for (int i = 0; i < 13; i++)
        if ((long long)s[i] != want[i] * scale) return false;
    return true;
}

extern "C" void kernel_launch(void* const* d_in, const int* in_sizes, int n_in,
                              void* d_out, int out_size) {
    if (n_in < 13) return;
    for (int i = 0; i < 13; i++) if (d_in[i] == nullptr) return;

    static const long long SIG_DICT[13] =
        {16777216,16777216,16777216,16777216,8192,8192,8192,
         16777216,16777216,2048,2048,2048,2048};
    static const long long SIG_ALPHA[13] =
        {16777216,16777216,16777216,16777216,8192,8192,
         2048,2048,2048,2048,8192,16777216,16777216};

    int order = 0;
    long long unit = 1;
    if (match_sig(in_sizes, SIG_DICT, 1))       { order = 0; unit = 1; }
    else if (match_sig(in_sizes, SIG_ALPHA, 1)) { order = 1; unit = 1; }
    else if (match_sig(in_sizes, SIG_DICT, 4))  { order = 0; unit = 4; }
    else if (match_sig(in_sizes, SIG_ALPHA, 4)) { order = 1; unit = 4; }

    const float *x_re, *x_im, *Wup_re, *Wup_im, *bias_re, *bias_im, *mrb;
    const float *Wd_re, *Wd_im, *g_re, *g_im, *be_re, *be_im;
    size_t sz[13];
    for (int i = 0; i < 13; i++) sz[i] = (size_t)((long long)in_sizes[i] / unit);
    size_t x_lim, wup_lim, wd_lim, bias_lim, ln_lim;

    if (order == 0) {
        x_re   = (const float*)d_in[0];  x_im   = (const float*)d_in[1];
        Wup_re = (const float*)d_in[2];  Wup_im = (const float*)d_in[3];
        bias_re = (const float*)d_in[4]; bias_im = (const float*)d_in[5];
        mrb    = (const float*)d_in[6];
        Wd_re  = (const float*)d_in[7];  Wd_im  = (const float*)d_in[8];
        g_re   = (const float*)d_in[9];  g_im   = (const float*)d_in[10];
        be_re  = (const float*)d_in[11]; be_im  = (const float*)d_in[12];
        x_lim = sz[0] < sz[1] ? sz[0] : sz[1];
        wup_lim = sz[2] < sz[3] ? sz[2] : sz[3];
        bias_lim = sz[4] < sz[5] ? sz[4] : sz[5];
        if (sz[6] < bias_lim) bias_lim = sz[6];
        wd_lim = sz[7] < sz[8] ? sz[7] : sz[8];
        ln_lim = sz[9];
        for (int i = 10; i <= 12; i++) if (sz[i] < ln_lim) ln_lim = sz[i];
    } else {
        Wd_im  = (const float*)d_in[0];  Wd_re  = (const float*)d_in[1];
        Wup_im = (const float*)d_in[2];  Wup_re = (const float*)d_in[3];
        bias_im = (const float*)d_in[4]; bias_re = (const float*)d_in[5];
        be_im  = (const float*)d_in[6];  be_re  = (const float*)d_in[7];
        g_im   = (const float*)d_in[8];  g_re   = (const float*)d_in[9];
        mrb    = (const float*)d_in[10];
        x_im   = (const float*)d_in[11]; x_re   = (const float*)d_in[12];
        wd_lim = sz[0] < sz[1] ? sz[0] : sz[1];
        wup_lim = sz[2] < sz[3] ? sz[2] : sz[3];
        bias_lim = sz[4] < sz[5] ? sz[4] : sz[5];
        if (sz[10] < bias_lim) bias_lim = sz[10];
        ln_lim = sz[6];
        for (int i = 7; i <= 9; i++) if (sz[i] < ln_lim) ln_lim = sz[i];
        x_lim = sz[11] < sz[12] ? sz[11] : sz[12];
    }

    const bool real_only = ((long long)out_size == 16777216LL);
    const size_t out_cap = (size_t)(long long)out_size;

    static bool attr_done = false;
    if (!attr_done) {
        cudaFuncSetAttribute(cgemm_nt<0>, cudaFuncAttributeMaxDynamicSharedMemorySize, SMEM_BYTES);
        cudaFuncSetAttribute(cgemm_nt<1>, cudaFuncAttributeMaxDynamicSharedMemorySize, SMEM_BYTES);
        attr_done = true;
    }

    // ---- pre-convert x, Wup, Wdown to bf16 planes (re, im, sum) ----
    uint32_t *cx[6], *cu[6], *cd[6];
    cudaGetSymbolAddress((void**)&cx[0], g_cX_hr);  cudaGetSymbolAddress((void**)&cx[1], g_cX_lr);
    cudaGetSymbolAddress((void**)&cx[2], g_cX_hi);  cudaGetSymbolAddress((void**)&cx[3], g_cX_li);
    cudaGetSymbolAddress((void**)&cx[4], g_cX_hs);  cudaGetSymbolAddress((void**)&cx[5], g_cX_ls);
    cudaGetSymbolAddress((void**)&cu[0], g_cWu_hr); cudaGetSymbolAddress((void**)&cu[1], g_cWu_lr);
    cudaGetSymbolAddress((void**)&cu[2], g_cWu_hi); cudaGetSymbolAddress((void**)&cu[3], g_cWu_li);
    cudaGetSymbolAddress((void**)&cu[4], g_cWu_hs); cudaGetSymbolAddress((void**)&cu[5], g_cWu_ls);
    cudaGetSymbolAddress((void**)&cd[0], g_cWd_hr); cudaGetSymbolAddress((void**)&cd[1], g_cWd_lr);
    cudaGetSymbolAddress((void**)&cd[2], g_cWd_hi); cudaGetSymbolAddress((void**)&cd[3], g_cWd_li);
    cudaGetSymbolAddress((void**)&cd[4], g_cWd_hs); cudaGetSymbolAddress((void**)&cd[5], g_cWd_ls);

    {
        int gx = (int)((XW + 255) / 256);
        conv_kernel<<<gx, 256>>>(x_re, x_im, cx[0], cx[1], cx[2], cx[3], cx[4], cx[5], XW, x_lim);
        int gw = (int)((WW + 255) / 256);
        conv_kernel<<<gw, 256>>>(Wup_re, Wup_im, cu[0], cu[1], cu[2], cu[3], cu[4], cu[5], WW, wup_lim);
        conv_kernel<<<gw, 256>>>(Wd_re, Wd_im, cd[0], cd[1], cd[2], cd[3], cd[4], cd[5], WW, wd_lim);
    }

    for (int c = 0; c < NCHUNKS; c++) {
        const int mb = c * MCHUNK;
        dim3 g1(CF / BN, MCHUNK / BM);
        cgemm_nt<0><<<g1, THREADS, SMEM_BYTES>>>(bias_re, bias_im, mrb,
                                                 mb, CF, CD, bias_lim);
        dim3 g2(CD / BN, MCHUNK / BM);
        cgemm_nt<1><<<g2, THREADS, SMEM_BYTES>>>(nullptr, nullptr, nullptr,
                                                 mb, CD, CF, 0);
        if (real_only) {
            ln_res_kernel<0><<<MCHUNK, 256>>>(x_re, x_im, g_re, g_im,
                                              be_re, be_im, (float*)d_out, mb,
                                              x_lim, ln_lim, out_cap);
        } else {
            ln_res_kernel<1><<<MCHUNK, 256>>>(x_re, x_im, g_re, g_im,
                                              be_re, be_im, (float*)d_out, mb,
                                              x_lim, ln_lim, out_cap);
        }
    }
}

// round 17
// speedup vs baseline: 1.6734x; 1.6734x over previous
#include <cuda_runtime.h>
#include <cuda_fp16.h>
#include <math.h>
#include <stdint.h>

#define LN_EPS 1e-5f

// Problem constants
constexpr int CB = 4, CS = 2048, CD = 2048, CF = 8192;
constexpr int CM = CB * CS;
constexpr int MCHUNK = 2048;
constexpr int NCHUNKS = CM / MCHUNK;

// GEMM tiling
constexpr int BM = 128, BN = 64, BK = 32;
constexpr int THREADS = 256;     // 8 warps: 4 (M) x 2 (N)
constexpr int RW = 16;           // smem row pitch in words (swizzled, no pad)

// Smem layout (words): per stage, 2 A planes (re-hi, im-hi) then 4 B planes.
constexpr int A_PL = BM * RW;                // 2048 words
constexpr int B_PL = BN * RW;                // 1024 words
constexpr int B_OFF = 2 * A_PL;              // 4096
constexpr int STAGE_W = 2 * A_PL + 4 * B_PL; // 8192 words = 32768 B
constexpr int SMEM_BYTES = 2 * STAGE_W * 4;  // 65536 B -> 2 CTAs/SM

// ---- device-global scratch: packed fp16x2 planes (word = k,k+1) ----
constexpr size_t XW = (size_t)CM * CD / 2;
constexpr size_t WW = (size_t)CF * CD / 2;
constexpr size_t UW = (size_t)MCHUNK * CF / 2;
__device__ __align__(16) uint32_t g_cX_hr[XW], g_cX_hi[XW];
__device__ __align__(16) uint32_t g_cWu_hr[WW], g_cWu_lr[WW], g_cWu_hi[WW], g_cWu_li[WW];
__device__ __align__(16) uint32_t g_cWd_hr[WW], g_cWd_lr[WW], g_cWd_hi[WW], g_cWd_li[WW];
__device__ __align__(16) uint32_t g_cUp_hr[UW], g_cUp_hi[UW];
__device__ __align__(16) float g_dn_re[(size_t)MCHUNK * CD];
__device__ __align__(16) float g_dn_im[(size_t)MCHUNK * CD];

// Pack two fp16 (hi only)
__device__ __forceinline__ uint32_t cvt2h(float x, float y) {
    __half xh = __float2half_rn(x);
    __half yh = __float2half_rn(y);
    return (uint32_t)__half_as_ushort(xh) | ((uint32_t)__half_as_ushort(yh) << 16);
}
// Split two fp32 into packed fp16 hi / lo words
__device__ __forceinline__ void split2h(float x, float y, uint32_t& hi, uint32_t& lo) {
    __half xh = __float2half_rn(x);
    __half yh = __float2half_rn(y);
    float xr = x - __half2float(xh);
    float yr = y - __half2float(yh);
    __half xl = __float2half_rn(xr);
    __half yl = __float2half_rn(yr);
    hi = (uint32_t)__half_as_ushort(xh) | ((uint32_t)__half_as_ushort(yh) << 16);
    lo = (uint32_t)__half_as_ushort(xl) | ((uint32_t)__half_as_ushort(yl) << 16);
}

__device__ __forceinline__ void mma16816(float* c, const uint32_t* a, const uint32_t* b) {
    asm volatile(
        "mma.sync.aligned.m16n8k16.row.col.f32.f16.f16.f32 "
        "{%0,%1,%2,%3}, {%4,%5,%6,%7}, {%8,%9}, {%0,%1,%2,%3};\n"
        : "+f"(c[0]), "+f"(c[1]), "+f"(c[2]), "+f"(c[3])
        : "r"(a[0]), "r"(a[1]), "r"(a[2]), "r"(a[3]), "r"(b[0]), "r"(b[1]));
}

#define LDSM4(r, addr) \
    asm volatile("ldmatrix.sync.aligned.m8n8.x4.shared.b16 {%0,%1,%2,%3}, [%4];" \
        : "=r"((r)[0]), "=r"((r)[1]), "=r"((r)[2]), "=r"((r)[3]) : "r"(addr))

__device__ __forceinline__ void cpasync16(uint32_t smem_bytes_addr, const void* g) {
    asm volatile("cp.async.cg.shared.global [%0], [%1], 16;\n"
                 :: "r"(smem_bytes_addr), "l"(g));
}
#define CP_COMMIT() asm volatile("cp.async.commit_group;\n")
template <int N>
__device__ __forceinline__ void cp_wait() {
    asm volatile("cp.async.wait_group %0;\n" :: "n"(N));
}

// Pre-conversion for A-side operands (x): fp32 -> fp16 hi planes only.
__global__ void __launch_bounds__(256)
conv_a_kernel(const float* __restrict__ re, const float* __restrict__ im,
              uint32_t* __restrict__ hr, uint32_t* __restrict__ hi_,
              size_t nwords, size_t lim) {
    size_t i = (size_t)blockIdx.x * 256 + threadIdx.x;
    if (i >= nwords) return;
    size_t e = 2 * i;
    float r0 = 0.f, r1 = 0.f, q0 = 0.f, q1 = 0.f;
    if (e + 2 <= lim) {
        float2 v = *reinterpret_cast<const float2*>(re + e);
        float2 w = *reinterpret_cast<const float2*>(im + e);
        r0 = v.x; r1 = v.y; q0 = w.x; q1 = w.y;
    }
    hr[i] = cvt2h(r0, r1);
    hi_[i] = cvt2h(q0, q1);
}

// Pre-conversion for B-side operands (weights): fp32 -> fp16 hi/lo planes.
__global__ void __launch_bounds__(256)
conv_b_kernel(const float* __restrict__ re, const float* __restrict__ im,
              uint32_t* __restrict__ hr, uint32_t* __restrict__ lr,
              uint32_t* __restrict__ hi_, uint32_t* __restrict__ li,
              size_t nwords, size_t lim) {
    size_t i = (size_t)blockIdx.x * 256 + threadIdx.x;
    if (i >= nwords) return;
    size_t e = 2 * i;
    float r0 = 0.f, r1 = 0.f, q0 = 0.f, q1 = 0.f;
    if (e + 2 <= lim) {
        float2 v = *reinterpret_cast<const float2*>(re + e);
        float2 w = *reinterpret_cast<const float2*>(im + e);
        r0 = v.x; r1 = v.y; q0 = w.x; q1 = w.y;
    }
    split2h(r0, r1, hr[i], lr[i]);
    split2h(q0, q1, hi_[i], li[i]);
}

// Complex NT GEMM, fp16 two-term split: a*b = ah*(bh+bl); A hi-only.
// 8 MMAs per k16 per (16x8) fragment.
// PHASE 0: A = g_cX (rows m_base+..), B = g_cWu, epi bias+modrelu -> g_cUp (fp16)
// PHASE 1: A = g_cUp (chunk-local), B = g_cWd, epi plain -> g_dn
template <int PHASE>
__global__ void __launch_bounds__(THREADS, 2)
cgemm_nt(const float* __restrict__ bias_re, const float* __restrict__ bias_im,
         const float* __restrict__ mrb,
         int m_base, int N, int K, size_t bias_lim) {
    extern __shared__ uint32_t s[];
    const uint32_t smem_b = (uint32_t)__cvta_generic_to_shared(s);

    const int tid = threadIdx.x;
    const int lane = tid & 31;
    const int warp = tid >> 5;
    const int wm = warp >> 1;
    const int wn = warp & 1;
    const int g  = lane >> 2;
    const int tg = lane & 3;
    const int m0 = blockIdx.y * BM;
    const int n0 = blockIdx.x * BN;

    const uint32_t* Apl[2];
    const uint32_t* Bpl[4];
    int a_row0;
    if (PHASE == 0) {
        Apl[0] = g_cX_hr; Apl[1] = g_cX_hi;
        Bpl[0] = g_cWu_hr; Bpl[1] = g_cWu_lr; Bpl[2] = g_cWu_hi; Bpl[3] = g_cWu_li;
        a_row0 = m_base;
    } else {
        Apl[0] = g_cUp_hr; Apl[1] = g_cUp_hi;
        Bpl[0] = g_cWd_hr; Bpl[1] = g_cWd_lr; Bpl[2] = g_cWd_hi; Bpl[3] = g_cWd_li;
        a_row0 = 0;
    }
    const int rw = K / 2;  // global plane row length in words

    const int lrow = lane & 7;
    const int quad = lane >> 3;

    // A-side ldmatrix offsets: quad = (chunk<<1)|rowhalf -> regs in mma order.
    int offA[2][2];
    {
        const int rselA = ((quad & 1) << 3) + lrow;
        const int cselA = quad >> 1;
#pragma unroll
        for (int mi = 0; mi < 2; mi++) {
            int r = wm * 32 + mi * 16 + rselA;
#pragma unroll
            for (int ks = 0; ks < 2; ks++)
                offA[mi][ks] = r * RW + (((ks * 2 + cselA) ^ ((r >> 1) & 3)) << 2);
        }
    }
    // B-side ldmatrix offsets: quad = (rowblock<<1)|chunk -> permute-free.
    int offB[2][2];
    {
        const int rselB = ((quad >> 1) << 3) + lrow;
        const int cselB = quad & 1;
#pragma unroll
        for (int p = 0; p < 2; p++) {
            int r = wn * 32 + p * 16 + rselB;
#pragma unroll
            for (int ks = 0; ks < 2; ks++)
                offB[p][ks] = r * RW + (((ks * 2 + cselB) ^ ((r >> 1) & 3)) << 2);
        }
    }

    float accRe[2][4][4], accIm[2][4][4];
#pragma unroll
    for (int mi = 0; mi < 2; mi++)
#pragma unroll
        for (int ni = 0; ni < 4; ni++)
#pragma unroll
            for (int r = 0; r < 4; r++) { accRe[mi][ni][r] = 0.f; accIm[mi][ni][r] = 0.f; }

    // Stage loader: A 2*128*4 + B 4*64*4 = 2048 16B chunks / 256 threads = 8.
    auto load_stage = [&](int buf, int k0) {
        const int kw0 = k0 >> 1;
        const uint32_t sb = smem_b + (uint32_t)buf * STAGE_W * 4;
#pragma unroll
        for (int t = 0; t < 8; t++) {
            int c = tid + t * THREADS;       // 0..2047
            const uint32_t* src;
            uint32_t dst;
            if (c < 1024) {                  // A: 2 planes x 128 rows x 4 chunks
                int p = c >> 9;
                int r = (c >> 2) & 127;
                int kc = c & 3;
                src = Apl[p] + (size_t)(a_row0 + m0 + r) * rw + kw0 + kc * 4;
                int w = r * RW + ((kc ^ ((r >> 1) & 3)) << 2);
                dst = sb + (uint32_t)(p * A_PL + w) * 4;
            } else {                         // B: 4 planes x 64 rows x 4 chunks
                int c2 = c - 1024;
                int p = c2 >> 8;
                int r = (c2 >> 2) & 63;
                int kc = c2 & 3;
                src = Bpl[p] + (size_t)(n0 + r) * rw + kw0 + kc * 4;
                int w = r * RW + ((kc ^ ((r >> 1) & 3)) << 2);
                dst = sb + (uint32_t)(B_OFF + p * B_PL + w) * 4;
            }
            cpasync16(dst, src);
        }
        CP_COMMIT();
    };

    const int NK = K / BK;
    load_stage(0, 0);

    for (int it = 0; it < NK; it++) {
        if (it + 1 < NK) {
            load_stage((it + 1) & 1, (it + 1) * BK);
            cp_wait<1>();
        } else {
            cp_wait<0>();
        }
        __syncthreads();

        const uint32_t sb = smem_b + (uint32_t)((it & 1) * STAGE_W) * 4;

#pragma unroll
        for (int ks = 0; ks < 2; ks++) {
            // B fragments: ldmatrix x4, regs land directly in [ni][2] order.
            uint32_t Brh[4][2], Brl[4][2], Bih[4][2], Bil[4][2];
#pragma unroll
            for (int p = 0; p < 2; p++) {
                const uint32_t b = sb + (uint32_t)(B_OFF + offB[p][ks]) * 4;
                LDSM4(&Brh[2 * p][0], b);
                LDSM4(&Brl[2 * p][0], b + B_PL * 4);
                LDSM4(&Bih[2 * p][0], b + 2 * B_PL * 4);
                LDSM4(&Bil[2 * p][0], b + 3 * B_PL * 4);
            }
            // A fragments: hi planes only.
            uint32_t Arh[2][4], Aih[2][4], nAih[2][4];
#pragma unroll
            for (int mi = 0; mi < 2; mi++) {
                const uint32_t a = sb + (uint32_t)offA[mi][ks] * 4;
                LDSM4(Arh[mi], a);
                LDSM4(Aih[mi], a + A_PL * 4);
#pragma unroll
                for (int r = 0; r < 4; r++)
                    nAih[mi][r] = Aih[mi][r] ^ 0x80008000u;
            }
#pragma unroll
            for (int mi = 0; mi < 2; mi++) {
#pragma unroll
                for (int ni = 0; ni < 4; ni++) {
                    // re = ar*br - ai*bi  (b = bh + bl)
                    mma16816(accRe[mi][ni], Arh[mi],  Brh[ni]);
                    mma16816(accRe[mi][ni], Arh[mi],  Brl[ni]);
                    mma16816(accRe[mi][ni], nAih[mi], Bih[ni]);
                    mma16816(accRe[mi][ni], nAih[mi], Bil[ni]);
                    // im = ar*bi + ai*br
                    mma16816(accIm[mi][ni], Arh[mi],  Bih[ni]);
                    mma16816(accIm[mi][ni], Arh[mi],  Bil[ni]);
                    mma16816(accIm[mi][ni], Aih[mi],  Brh[ni]);
                    mma16816(accIm[mi][ni], Aih[mi],  Brl[ni]);
                }
            }
        }
        __syncthreads();
    }

    // ---- epilogue ----
    const bool bias_ok = (PHASE != 0) || ((size_t)n0 + BN <= bias_lim);
#pragma unroll
    for (int mi = 0; mi < 2; mi++) {
#pragma unroll
        for (int ni = 0; ni < 4; ni++) {
            const int col = n0 + wn * 32 + ni * 8 + 2 * tg;   // even
#pragma unroll
            for (int h = 0; h < 2; h++) {
                const int row = m0 + wm * 32 + mi * 16 + g + h * 8;
                float re0 = accRe[mi][ni][2 * h], re1 = accRe[mi][ni][2 * h + 1];
                float im0 = accIm[mi][ni][2 * h], im1 = accIm[mi][ni][2 * h + 1];
                if (PHASE == 0) {
                    float br0 = 0.f, br1 = 0.f, bi0 = 0.f, bi1 = 0.f, mb0 = 0.f, mb1 = 0.f;
                    if (bias_ok) {
                        br0 = bias_re[col]; br1 = bias_re[col + 1];
                        bi0 = bias_im[col]; bi1 = bias_im[col + 1];
                        mb0 = mrb[col];     mb1 = mrb[col + 1];
                    }
                    re0 += br0; im0 += bi0; re1 += br1; im1 += bi1;
                    float mag0 = sqrtf(re0 * re0 + im0 * im0);
                    float mag1 = sqrtf(re1 * re1 + im1 * im1);
                    float s0 = fmaxf(mag0 + mb0, 0.f) / (mag0 + LN_EPS);
                    float s1 = fmaxf(mag1 + mb1, 0.f) / (mag1 + LN_EPS);
                    re0 *= s0; im0 *= s0; re1 *= s1; im1 *= s1;
                    const size_t wo = (size_t)row * (N / 2) + (col >> 1);
                    g_cUp_hr[wo] = cvt2h(re0, re1);
                    g_cUp_hi[wo] = cvt2h(im0, im1);
                } else {
                    const size_t off = (size_t)row * N + col;
                    *reinterpret_cast<float2*>(g_dn_re + off) = make_float2(re0, re1);
                    *reinterpret_cast<float2*>(g_dn_im + off) = make_float2(im0, im1);
                }
            }
        }
    }
}

// Complex LayerNorm over D + residual, one block per (chunk-local) token row.
template <int OUT_MODE>
__global__ void __launch_bounds__(256)
ln_res_kernel(const float* __restrict__ xr, const float* __restrict__ xi,
              const float* __restrict__ gr, const float* __restrict__ gi,
              const float* __restrict__ br, const float* __restrict__ bi,
              float* __restrict__ out, int m_base,
              size_t x_lim, size_t p_lim, size_t out_cap) {
    const int m = blockIdx.x;
    const size_t base = (size_t)m * CD;
    const size_t gbase = (size_t)(m_base + m) * CD;
    const int tid = threadIdx.x;
    const bool x_ok = (gbase + CD) <= x_lim;
    const bool p_ok = (size_t)CD <= p_lim;

    float sr = 0.f, si = 0.f, sq = 0.f;
    for (int d = tid; d < CD; d += 256) {
        float r = g_dn_re[base + d];
        float q = g_dn_im[base + d];
        sr += r; si += q; sq += r * r + q * q;
    }
    __shared__ float red0[256], red1[256], red2[256];
    red0[tid] = sr; red1[tid] = si; red2[tid] = sq;
    __syncthreads();
    for (int st = 128; st > 0; st >>= 1) {
        if (tid < st) {
            red0[tid] += red0[tid + st];
            red1[tid] += red1[tid + st];
            red2[tid] += red2[tid + st];
        }
        __syncthreads();
    }
    const float inv_d = 1.f / (float)CD;
    const float mur = red0[0] * inv_d;
    const float mui = red1[0] * inv_d;
    const float var = red2[0] * inv_d - (mur * mur + mui * mui);
    const float rstd = rsqrtf(var + LN_EPS);

    for (int d = tid; d < CD; d += 256) {
        float zr = (g_dn_re[base + d] - mur) * rstd;
        float zi = (g_dn_im[base + d] - mui) * rstd;
        float g_r = p_ok ? gr[d] : 1.f;
        float g_i = p_ok ? gi[d] : 0.f;
        float b_r = p_ok ? br[d] : 0.f;
        float b_i = p_ok ? bi[d] : 0.f;
        float xre = x_ok ? xr[gbase + d] : 0.f;
        float xim = x_ok ? xi[gbase + d] : 0.f;
        float o_r = g_r * zr - g_i * zi + b_r + xre;
        float o_i = g_r * zi + g_i * zr + b_i + xim;
        if (OUT_MODE == 0) {
            const size_t fo = gbase + d;
            if (fo < out_cap) out[fo] = o_r;
        } else {
            const size_t fo = 2 * (gbase + d);
            if (fo + 1 < out_cap) { out[fo] = o_r; out[fo + 1] = o_i; }
        }
    }
}

// ---------------- host-side binding ----------------
static bool match_sig(const int* s, const long long* want, long long scale) {
    for (int i = 0; i < 13; i++)
        if ((long long)s[i] != want[i] * scale) return false;
    return true;
}

extern "C" void kernel_launch(void* const* d_in, const int* in_sizes, int n_in,
                              void* d_out, int out_size) {
    if (n_in < 13) return;
    for (int i = 0; i < 13; i++) if (d_in[i] == nullptr) return;

    static const long long SIG_DICT[13] =
        {16777216,16777216,16777216,16777216,8192,8192,8192,
         16777216,16777216,2048,2048,2048,2048};
    static const long long SIG_ALPHA[13] =
        {16777216,16777216,16777216,16777216,8192,8192,
         2048,2048,2048,2048,8192,16777216,16777216};

    int order = 0;
    long long unit = 1;
    if (match_sig(in_sizes, SIG_DICT, 1))       { order = 0; unit = 1; }
    else if (match_sig(in_sizes, SIG_ALPHA, 1)) { order = 1; unit = 1; }
    else if (match_sig(in_sizes, SIG_DICT, 4))  { order = 0; unit = 4; }
    else if (match_sig(in_sizes, SIG_ALPHA, 4)) { order = 1; unit = 4; }

    const float *x_re, *x_im, *Wup_re, *Wup_im, *bias_re, *bias_im, *mrb;
    const float *Wd_re, *Wd_im, *g_re, *g_im, *be_re, *be_im;
    size_t sz[13];
    for (int i = 0; i < 13; i++) sz[i] = (size_t)((long long)in_sizes[i] / unit);
    size_t x_lim, wup_lim, wd_lim, bias_lim, ln_lim;

    if (order == 0) {
        x_re   = (const float*)d_in[0];  x_im   = (const float*)d_in[1];
        Wup_re = (const float*)d_in[2];  Wup_im = (const float*)d_in[3];
        bias_re = (const float*)d_in[4]; bias_im = (const float*)d_in[5];
        mrb    = (const float*)d_in[6];
        Wd_re  = (const float*)d_in[7];  Wd_im  = (const float*)d_in[8];
        g_re   = (const float*)d_in[9];  g_im   = (const float*)d_in[10];
        be_re  = (const float*)d_in[11]; be_im  = (const float*)d_in[12];
        x_lim = sz[0] < sz[1] ? sz[0] : sz[1];
        wup_lim = sz[2] < sz[3] ? sz[2] : sz[3];
        bias_lim = sz[4] < sz[5] ? sz[4] : sz[5];
        if (sz[6] < bias_lim) bias_lim = sz[6];
        wd_lim = sz[7] < sz[8] ? sz[7] : sz[8];
        ln_lim = sz[9];
        for (int i = 10; i <= 12; i++) if (sz[i] < ln_lim) ln_lim = sz[i];
    } else {
        Wd_im  = (const float*)d_in[0];  Wd_re  = (const float*)d_in[1];
        Wup_im = (const float*)d_in[2];  Wup_re = (const float*)d_in[3];
        bias_im = (const float*)d_in[4]; bias_re = (const float*)d_in[5];
        be_im  = (const float*)d_in[6];  be_re  = (const float*)d_in[7];
        g_im   = (const float*)d_in[8];  g_re   = (const float*)d_in[9];
        mrb    = (const float*)d_in[10];
        x_im   = (const float*)d_in[11]; x_re   = (const float*)d_in[12];
        wd_lim = sz[0] < sz[1] ? sz[0] : sz[1];
        wup_lim = sz[2] < sz[3] ? sz[2] : sz[3];
        bias_lim = sz[4] < sz[5] ? sz[4] : sz[5];
        if (sz[10] < bias_lim) bias_lim = sz[10];
        ln_lim = sz[6];
        for (int i = 7; i <= 9; i++) if (sz[i] < ln_lim) ln_lim = sz[i];
        x_lim = sz[11] < sz[12] ? sz[11] : sz[12];
    }

    const bool real_only = ((long long)out_size == 16777216LL);
    const size_t out_cap = (size_t)(long long)out_size;

    static bool attr_done = false;
    if (!attr_done) {
        cudaFuncSetAttribute(cgemm_nt<0>, cudaFuncAttributeMaxDynamicSharedMemorySize, SMEM_BYTES);
        cudaFuncSetAttribute(cgemm_nt<1>, cudaFuncAttributeMaxDynamicSharedMemorySize, SMEM_BYTES);
        attr_done = true;
    }

    // ---- pre-convert: x -> fp16 hi planes; Wup/Wd -> fp16 hi/lo planes ----
    uint32_t *cx0, *cx1;
    uint32_t *cu0, *cu1, *cu2, *cu3, *cd0, *cd1, *cd2, *cd3;
    cudaGetSymbolAddress((void**)&cx0, g_cX_hr);  cudaGetSymbolAddress((void**)&cx1, g_cX_hi);
    cudaGetSymbolAddress((void**)&cu0, g_cWu_hr); cudaGetSymbolAddress((void**)&cu1, g_cWu_lr);
    cudaGetSymbolAddress((void**)&cu2, g_cWu_hi); cudaGetSymbolAddress((void**)&cu3, g_cWu_li);
    cudaGetSymbolAddress((void**)&cd0, g_cWd_hr); cudaGetSymbolAddress((void**)&cd1, g_cWd_lr);
    cudaGetSymbolAddress((void**)&cd2, g_cWd_hi); cudaGetSymbolAddress((void**)&cd3, g_cWd_li);

    {
        int gx = (int)((XW + 255) / 256);
        conv_a_kernel<<<gx, 256>>>(x_re, x_im, cx0, cx1, XW, x_lim);
        int gw = (int)((WW + 255) / 256);
        conv_b_kernel<<<gw, 256>>>(Wup_re, Wup_im, cu0, cu1, cu2, cu3, WW, wup_lim);
        conv_b_kernel<<<gw, 256>>>(Wd_re, Wd_im, cd0, cd1, cd2, cd3, WW, wd_lim);
    }

    for (int c = 0; c < NCHUNKS; c++) {
        const int mb = c * MCHUNK;
        dim3 g1(CF / BN, MCHUNK / BM);
        cgemm_nt<0><<<g1, THREADS, SMEM_BYTES>>>(bias_re, bias_im, mrb,
                                                 mb, CF, CD, bias_lim);
        dim3 g2(CD / BN, MCHUNK / BM);
        cgemm_nt<1><<<g2, THREADS, SMEM_BYTES>>>(nullptr, nullptr, nullptr,
                                                 mb, CD, CF, 0);
        if (real_only) {
            ln_res_kernel<0><<<MCHUNK, 256>>>(x_re, x_im, g_re, g_im,
                                              be_re, be_im, (float*)d_out, mb,
                                              x_lim, ln_lim, out_cap);
        } else {
            ln_res_kernel<1><<<MCHUNK, 256>>>(x_re, x_im, g_re, g_im,
                                              be_re, be_im, (float*)d_out, mb,
                                              x_lim, ln_lim, out_cap);
        }
    }
}